// round 12
// baseline (speedup 1.0000x reference)
#include <cuda_runtime.h>
#include <cuda_bf16.h>
#include <math.h>

// Problem dims (fixed by the reference)
#define T_STEPS 512
#define BATCH   256
#define DIM     1024
#define HID     1024
#define OUTD    5

// Recurrence: 128 CTAs = 8 m-groups(32) x 16 n-tiles(64), 512 threads.
#define GRID_P  128
#define MT      32
#define NT      64
#define RKQ     2048          // Red per-k-eighth stride (32 rows x 64 cols fp32)

// Scratch
__device__ float          g_E[(size_t)T_STEPS * BATCH * HID];     // fp32 input proj
__device__ __nv_bfloat16  g_hbf[2][(size_t)BATCH * HID];          // bf16 h transport
__device__ float          g_hfinal[(size_t)BATCH * HID];          // fp32 final h
__device__ unsigned       g_grp[8][32];                           // per-m-group barrier ctrs

// ---------------------------------------------------------------------------
__device__ __forceinline__ void mma_bf16(float d[4],
                                         unsigned a0, unsigned a1,
                                         unsigned a2, unsigned a3,
                                         unsigned b0, unsigned b1)
{
    asm volatile(
        "mma.sync.aligned.m16n8k16.row.col.f32.bf16.bf16.f32 "
        "{%0,%1,%2,%3}, {%4,%5,%6,%7}, {%8,%9}, {%0,%1,%2,%3};"
        : "+f"(d[0]), "+f"(d[1]), "+f"(d[2]), "+f"(d[3])
        : "r"(a0), "r"(a1), "r"(a2), "r"(a3), "r"(b0), "r"(b1));
}

__device__ __forceinline__ float sigmoidf_fast(float x)
{
    return 1.0f / (1.0f + __expf(-x));
}

// ---------------------------------------------------------------------------
// E = x @ W_in^T + b_in, single-pass bf16 tensor-core GEMM (validated R7/R8).
// ---------------------------------------------------------------------------
__global__ void __launch_bounds__(256, 2)
egemm_bf16(const float* __restrict__ X,     // [131072, 1024]
           const float* __restrict__ Wg,    // [1024, 1024]
           const float* __restrict__ bias,  // [1024]
           float* __restrict__ E)
{
    extern __shared__ unsigned es[];
    unsigned* Ah = es;              // 8192 words (32KB)
    unsigned* Bh = es + 8192;       // 4096 words (16KB)

    const int tid  = threadIdx.x;
    const int lane = tid & 31;
    const int w    = tid >> 5;
    const int qid  = lane >> 2;
    const int c    = lane & 3;
    const int g    = w >> 1;
    const int subm = (w & 1) * 16;

    const int n0 = blockIdx.x * 64;
    const int m0 = blockIdx.y * 128;

    const int srow = tid >> 3;
    const int ssl  = tid & 7;
    const int sx   = ssl & 3;

    float acc[4][2][4];
    #pragma unroll
    for (int a = 0; a < 4; a++)
        #pragma unroll
        for (int b = 0; b < 2; b++)
            #pragma unroll
            for (int d = 0; d < 4; d++) acc[a][b][d] = 0.0f;

    for (int ch = 0; ch < 8; ch++) {
        __syncthreads();
        const float* xbase = X + (size_t)(m0 + srow) * 1024 + ch * 128 + ssl * 16;
        #pragma unroll
        for (int jj = 0; jj < 4; jj++) {
            const float4* p = (const float4*)(xbase + (size_t)jj * 32 * 1024);
            float4 f0 = p[0], f1 = p[1], f2 = p[2], f3 = p[3];
            unsigned h[8];
            {
                __nv_bfloat162 b0 = __float22bfloat162_rn(make_float2(f0.x, f0.y));
                __nv_bfloat162 b1 = __float22bfloat162_rn(make_float2(f0.z, f0.w));
                __nv_bfloat162 b2 = __float22bfloat162_rn(make_float2(f1.x, f1.y));
                __nv_bfloat162 b3 = __float22bfloat162_rn(make_float2(f1.z, f1.w));
                __nv_bfloat162 b4 = __float22bfloat162_rn(make_float2(f2.x, f2.y));
                __nv_bfloat162 b5 = __float22bfloat162_rn(make_float2(f2.z, f2.w));
                __nv_bfloat162 b6 = __float22bfloat162_rn(make_float2(f3.x, f3.y));
                __nv_bfloat162 b7 = __float22bfloat162_rn(make_float2(f3.z, f3.w));
                h[0] = *(unsigned*)&b0; h[1] = *(unsigned*)&b1;
                h[2] = *(unsigned*)&b2; h[3] = *(unsigned*)&b3;
                h[4] = *(unsigned*)&b4; h[5] = *(unsigned*)&b5;
                h[6] = *(unsigned*)&b6; h[7] = *(unsigned*)&b7;
            }
            uint2* dh = (uint2*)&Ah[jj * 2048 + ssl * 256 + srow * 8];
            dh[0 ^ sx] = make_uint2(h[0], h[4]);
            dh[1 ^ sx] = make_uint2(h[1], h[5]);
            dh[2 ^ sx] = make_uint2(h[2], h[6]);
            dh[3 ^ sx] = make_uint2(h[3], h[7]);
        }
        #pragma unroll
        for (int jj = 0; jj < 2; jj++) {
            int nrow = srow + jj * 32;
            const float4* p = (const float4*)(Wg + (size_t)(n0 + nrow) * 1024
                                              + ch * 128 + ssl * 16);
            float4 f0 = p[0], f1 = p[1], f2 = p[2], f3 = p[3];
            unsigned h[8];
            {
                __nv_bfloat162 b0 = __float22bfloat162_rn(make_float2(f0.x, f0.y));
                __nv_bfloat162 b1 = __float22bfloat162_rn(make_float2(f0.z, f0.w));
                __nv_bfloat162 b2 = __float22bfloat162_rn(make_float2(f1.x, f1.y));
                __nv_bfloat162 b3 = __float22bfloat162_rn(make_float2(f1.z, f1.w));
                __nv_bfloat162 b4 = __float22bfloat162_rn(make_float2(f2.x, f2.y));
                __nv_bfloat162 b5 = __float22bfloat162_rn(make_float2(f2.z, f2.w));
                __nv_bfloat162 b6 = __float22bfloat162_rn(make_float2(f3.x, f3.y));
                __nv_bfloat162 b7 = __float22bfloat162_rn(make_float2(f3.z, f3.w));
                h[0] = *(unsigned*)&b0; h[1] = *(unsigned*)&b1;
                h[2] = *(unsigned*)&b2; h[3] = *(unsigned*)&b3;
                h[4] = *(unsigned*)&b4; h[5] = *(unsigned*)&b5;
                h[6] = *(unsigned*)&b6; h[7] = *(unsigned*)&b7;
            }
            uint2* dh = (uint2*)&Bh[ssl * 512 + nrow * 8];
            dh[0 ^ sx] = make_uint2(h[0], h[4]);
            dh[1 ^ sx] = make_uint2(h[1], h[5]);
            dh[2 ^ sx] = make_uint2(h[2], h[6]);
            dh[3 ^ sx] = make_uint2(h[3], h[7]);
        }
        __syncthreads();

        #pragma unroll
        for (int sl = 0; sl < 8; sl++) {
            int axw = g * 2048 + sl * 256 + (subm + qid) * 8 + 2 * (c ^ (sl & 3));
            uint2 ah0 = *(const uint2*)&Ah[axw];
            uint2 ah1 = *(const uint2*)&Ah[axw + 64];
            #pragma unroll
            for (int ng = 0; ng < 4; ng++) {
                int bxw = sl * 512 + ng * 128 + qid * 8 + 2 * (c ^ (sl & 3));
                uint2 bh0 = *(const uint2*)&Bh[bxw];
                uint2 bh1 = *(const uint2*)&Bh[bxw + 64];
                mma_bf16(acc[ng][0], ah0.x, ah1.x, ah0.y, ah1.y, bh0.x, bh0.y);
                mma_bf16(acc[ng][1], ah0.x, ah1.x, ah0.y, ah1.y, bh1.x, bh1.y);
            }
        }
    }

    const int mrow = m0 + w * 16 + qid;
    #pragma unroll
    for (int ng = 0; ng < 4; ng++) {
        #pragma unroll
        for (int hh = 0; hh < 2; hh++) {
            int col = n0 + ng * 16 + hh * 8 + 2 * c;
            float2 b2 = *(const float2*)(bias + col);
            float2 o0, o1;
            o0.x = acc[ng][hh][0] + b2.x; o0.y = acc[ng][hh][1] + b2.y;
            o1.x = acc[ng][hh][2] + b2.x; o1.y = acc[ng][hh][3] + b2.y;
            *(float2*)&E[(size_t)mrow * 1024 + col]       = o0;
            *(float2*)&E[(size_t)(mrow + 8) * 1024 + col] = o1;
        }
    }
}

// ---------------------------------------------------------------------------
__global__ void h0_to_bf16(const float* __restrict__ h0)
{
    int i = blockIdx.x * 256 + threadIdx.x;
    g_hbf[1][i] = __float2bfloat16(h0[i]);
}

// Dummy launch: shifts ncu's fixed capture slot onto rnn_persistent.
__global__ void ncu_shift_dummy() {}

// ---------------------------------------------------------------------------
// Per-m-group barrier: 16 CTAs, release/acquire atomics, monotonic counter.
// ---------------------------------------------------------------------------
__device__ __forceinline__ void group_barrier(int grp, unsigned target)
{
    __syncthreads();
    if (threadIdx.x == 0) {
        unsigned* ctr = &g_grp[grp][0];
        asm volatile("red.release.gpu.global.add.u32 [%0], %1;"
                     :: "l"(ctr), "r"(1u) : "memory");
        unsigned v;
        do {
            asm volatile("ld.acquire.gpu.global.u32 %0, [%1];"
                         : "=r"(v) : "l"(ctr) : "memory");
        } while (v < target);
    }
    __syncthreads();
}

// ---------------------------------------------------------------------------
// Persistent recurrence, R11: 512 threads / 16 warps (4 per SMSP) to halve
// latency exposure (R10 profile: issue 17.9%, occ 12.5% -> warp starvation).
// Warp w = (kq = w>>1 in 0..7, nh = w&1): 32m x 32n x 128k partial, 64 MMAs.
// 8-way k-reduction through Red (reuses As) with XOR swizzle (RSTR=64,
// col ^ (row&7)<<3) to avoid write bank conflicts.
// smem: Ws 128KB + As/Red 64KB = 192KB. Regs <=128 (launch_bounds 512,1).
// ---------------------------------------------------------------------------
__global__ void __launch_bounds__(512, 1)
rnn_persistent(const float* __restrict__ W_h,
               const float* __restrict__ b_h)
{
    extern __shared__ unsigned smw[];
    unsigned* Ws = smw;              // 32768 words (128KB)
    unsigned* As = smw + 32768;      // 16384 words (64KB), later Red
    float*    Red = (float*)As;

    const int tid  = threadIdx.x;
    const int lane = tid & 31;
    const int w    = tid >> 5;       // 0..15
    const int qid  = lane >> 2;
    const int c    = lane & 3;
    const int kq   = w >> 1;         // k-eighth (8 slices of k16)
    const int nh   = w & 1;          // n-half (32 cols)
    const int cta  = blockIdx.x;
    const int grp  = cta >> 4;
    const int m0   = grp * MT;
    const int n0   = (cta & 15) * NT;

    // ---- fill Ws (once): fp32 -> bf16x2, fragment-shuffled (R8 layout) ----
    for (int i = tid; i < NT * 512; i += 512) {
        int n  = i >> 9;
        int kp = i & 511;
        int k  = kp * 2;
        int s  = k >> 4;
        int p  = (k & 15) >> 1;
        float2 wv = *(const float2*)(W_h + (size_t)(n0 + n) * HID + k);
        __nv_bfloat162 bb = __float22bfloat162_rn(wv);
        Ws[s * 512 + n * 8 + (p & 3) * 2 + (p >> 2)] = *(unsigned*)&bb;
    }

    // epilogue coords: row (0..31), 4 cols from ecol
    const int erow = tid >> 4;
    const int ecol = (tid & 15) * 4;
    const int esw  = ecol ^ ((erow & 7) << 3);
    const float4 bh4 = *(const float4*)(b_h + n0 + ecol);
    __syncthreads();

    // staging map: row = tid>>4, s4 = tid&15; slices s = s4 + 16*j (j 0..3)
    const int srow = tid >> 4;
    const int s4   = tid & 15;

    for (int t = 0; t < T_STEPS; t++) {
        const __nv_bfloat16* hin  = g_hbf[(t + 1) & 1];
        __nv_bfloat16*       hout = g_hbf[t & 1];

        // ---- bulk load h tile: 8 int4/thread, front-batched ----
        const __nv_bfloat16* gsrc = hin + (size_t)(m0 + srow) * HID;
        int4 v[8];
        #pragma unroll
        for (int j = 0; j < 4; j++) {
            const int s = s4 + 16 * j;
            v[2 * j]     = __ldcg((const int4*)(gsrc + s * 16));
            v[2 * j + 1] = __ldcg((const int4*)(gsrc + s * 16 + 8));
        }

        // epilogue E operand (overlaps with step)
        float4 e4 = __ldg((const float4*)(g_E
                        + ((size_t)t * BATCH + m0 + erow) * HID + n0 + ecol));

        // ---- stage 4 slices, one sync ----
        #pragma unroll
        for (int j = 0; j < 4; j++) {
            const int s  = s4 + 16 * j;
            const int sx = s & 3;
            uint2* dp = (uint2*)(As + s * 256 + srow * 8);
            int4 a = v[2 * j], b = v[2 * j + 1];
            dp[0 ^ sx] = make_uint2(a.x, b.x);
            dp[1 ^ sx] = make_uint2(a.y, b.y);
            dp[2 ^ sx] = make_uint2(a.z, b.z);
            dp[3 ^ sx] = make_uint2(a.w, b.w);
        }
        __syncthreads();

        // ---- MMA: warp (kq, nh), 8 slices x 8 MMAs ----
        float d[2][4][4];
        #pragma unroll
        for (int mg = 0; mg < 2; mg++)
            #pragma unroll
            for (int ng = 0; ng < 4; ng++)
                #pragma unroll
                for (int j = 0; j < 4; j++) d[mg][ng][j] = 0.0f;

        #pragma unroll
        for (int i = 0; i < 8; i++) {
            const int s = kq * 8 + i;
            const unsigned* Ab = As + s * 256 + 2 * (c ^ (s & 3));
            uint2 a0L = *(const uint2*)(Ab + qid * 8);
            uint2 a0H = *(const uint2*)(Ab + (qid + 8) * 8);
            uint2 a1L = *(const uint2*)(Ab + (qid + 16) * 8);
            uint2 a1H = *(const uint2*)(Ab + (qid + 24) * 8);
            const unsigned* Wb = Ws + s * 512 + (nh * 32 + qid) * 8 + 2 * c;
            uint2 b0 = *(const uint2*)(Wb);
            uint2 b1 = *(const uint2*)(Wb + 64);
            uint2 b2 = *(const uint2*)(Wb + 128);
            uint2 b3 = *(const uint2*)(Wb + 192);
            mma_bf16(d[0][0], a0L.x, a0H.x, a0L.y, a0H.y, b0.x, b0.y);
            mma_bf16(d[0][1], a0L.x, a0H.x, a0L.y, a0H.y, b1.x, b1.y);
            mma_bf16(d[0][2], a0L.x, a0H.x, a0L.y, a0H.y, b2.x, b2.y);
            mma_bf16(d[0][3], a0L.x, a0H.x, a0L.y, a0H.y, b3.x, b3.y);
            mma_bf16(d[1][0], a1L.x, a1H.x, a1L.y, a1H.y, b0.x, b0.y);
            mma_bf16(d[1][1], a1L.x, a1H.x, a1L.y, a1H.y, b1.x, b1.y);
            mma_bf16(d[1][2], a1L.x, a1H.x, a1L.y, a1H.y, b2.x, b2.y);
            mma_bf16(d[1][3], a1L.x, a1H.x, a1L.y, a1H.y, b3.x, b3.y);
        }
        __syncthreads();   // all h-tile reads complete -> As reusable as Red

        // ---- write fp32 k-partials into Red (XOR-swizzled) ----
        #pragma unroll
        for (int mg = 0; mg < 2; mg++) {
            #pragma unroll
            for (int ng = 0; ng < 4; ng++) {
                const int ncol = nh * 32 + ng * 8 + 2 * c;
                const int r1 = mg * 16 + qid;
                const int r2 = r1 + 8;
                *(float2*)(Red + kq * RKQ + r1 * 64 + (ncol ^ ((r1 & 7) << 3)))
                    = make_float2(d[mg][ng][0], d[mg][ng][1]);
                *(float2*)(Red + kq * RKQ + r2 * 64 + (ncol ^ ((r2 & 7) << 3)))
                    = make_float2(d[mg][ng][2], d[mg][ng][3]);
            }
        }
        __syncthreads();

        // ---- epilogue: reduce 8 k-partials, + b_h + E, sigmoid ----
        const float* rb = Red + erow * 64 + esw;
        float4 p0 = *(const float4*)(rb);
        float4 p1 = *(const float4*)(rb + 1 * RKQ);
        float4 p2 = *(const float4*)(rb + 2 * RKQ);
        float4 p3 = *(const float4*)(rb + 3 * RKQ);
        float4 p4 = *(const float4*)(rb + 4 * RKQ);
        float4 p5 = *(const float4*)(rb + 5 * RKQ);
        float4 p6 = *(const float4*)(rb + 6 * RKQ);
        float4 p7 = *(const float4*)(rb + 7 * RKQ);
        float4 f;
        f.x = ((p0.x + p1.x) + (p2.x + p3.x)) + ((p4.x + p5.x) + (p6.x + p7.x));
        f.y = ((p0.y + p1.y) + (p2.y + p3.y)) + ((p4.y + p5.y) + (p6.y + p7.y));
        f.z = ((p0.z + p1.z) + (p2.z + p3.z)) + ((p4.z + p5.z) + (p6.z + p7.z));
        f.w = ((p0.w + p1.w) + (p2.w + p3.w)) + ((p4.w + p5.w) + (p6.w + p7.w));

        float sx0 = sigmoidf_fast(f.x + bh4.x + e4.x);
        float sy0 = sigmoidf_fast(f.y + bh4.y + e4.y);
        float sz0 = sigmoidf_fast(f.z + bh4.z + e4.z);
        float sw0 = sigmoidf_fast(f.w + bh4.w + e4.w);

        __nv_bfloat162 pa = __float22bfloat162_rn(make_float2(sx0, sy0));
        __nv_bfloat162 pb = __float22bfloat162_rn(make_float2(sz0, sw0));
        *(uint2*)(hout + (size_t)(m0 + erow) * HID + n0 + ecol)
            = make_uint2(*(unsigned*)&pa, *(unsigned*)&pb);

        if (t == T_STEPS - 1) {
            *(float4*)(g_hfinal + (size_t)(m0 + erow) * HID + n0 + ecol)
                = make_float4(sx0, sy0, sz0, sw0);
        } else {
            group_barrier(grp, 16u * (t + 1));
        }
    }
}

// ---------------------------------------------------------------------------
// Final head (all 128 threads participate in the dot product)
// ---------------------------------------------------------------------------
__global__ void finalize_kernel(const float* __restrict__ h,
                                const float* __restrict__ state_in,
                                const float* __restrict__ W_o,
                                const float* __restrict__ b_o,
                                float* __restrict__ out)
{
    const int b    = blockIdx.x;
    const int tid  = threadIdx.x;
    const int lane = tid & 31;
    const int wid  = tid >> 5;

    __shared__ float red[4][OUTD];
    __shared__ float logits[OUTD];

    float acc[OUTD];
    #pragma unroll
    for (int o = 0; o < OUTD; o++) acc[o] = 0.0f;
    for (int k = tid; k < HID; k += 128) {
        float hv = h[(size_t)b * HID + k];
        #pragma unroll
        for (int o = 0; o < OUTD; o++)
            acc[o] += hv * W_o[(size_t)o * HID + k];
    }
    #pragma unroll
    for (int o = 0; o < OUTD; o++) {
        float v = acc[o];
        #pragma unroll
        for (int s = 16; s > 0; s >>= 1)
            v += __shfl_xor_sync(0xffffffff, v, s);
        if (lane == 0) red[wid][o] = v;
    }
    __syncthreads();

    if (tid == 0) {
        #pragma unroll
        for (int o = 0; o < OUTD; o++)
            logits[o] = red[0][o] + red[1][o] + red[2][o] + red[3][o] + b_o[o];
        float m = logits[0];
        #pragma unroll
        for (int o = 1; o < OUTD; o++) m = fmaxf(m, logits[o]);
        float s = 0.0f;
        #pragma unroll
        for (int o = 0; o < OUTD; o++) s += expf(logits[o] - m);
        float lse = m + logf(s);
        #pragma unroll
        for (int o = 0; o < OUTD; o++)
            out[(size_t)b * OUTD + o] = logits[o] - lse;
    }

    float* hid_out = out + (size_t)BATCH * OUTD;
    float* st_out  = hid_out + (size_t)BATCH * HID;
    for (int k = tid; k < HID; k += blockDim.x) {
        hid_out[(size_t)b * HID + k] = h[(size_t)b * HID + k];
        st_out[(size_t)b * HID + k]  = state_in[(size_t)b * HID + k];
    }
}

extern "C" void kernel_launch(void* const* d_in, const int* in_sizes, int n_in,
                              void* d_out, int out_size)
{
    const float* x    = (const float*)d_in[0];
    const float* h0   = (const float*)d_in[1];
    const float* st   = (const float*)d_in[2];
    const float* W_in = (const float*)d_in[3];
    const float* b_in = (const float*)d_in[4];
    const float* W_h  = (const float*)d_in[5];
    const float* b_h  = (const float*)d_in[6];
    const float* W_o  = (const float*)d_in[7];
    const float* b_o  = (const float*)d_in[8];
    float* out = (float*)d_out;

    float* Eptr = nullptr;
    float* hfin = nullptr;
    unsigned* grpptr = nullptr;
    cudaGetSymbolAddress((void**)&Eptr, g_E);
    cudaGetSymbolAddress((void**)&hfin, g_hfinal);
    cudaGetSymbolAddress((void**)&grpptr, g_grp);

    cudaMemsetAsync(grpptr, 0, 8 * 32 * sizeof(unsigned));

    // 0) h0 -> bf16 transport buffer
    h0_to_bf16<<<(BATCH * HID) / 256, 256>>>(h0);

    // 1) E = x @ W_in^T + b_in (single-pass bf16, fp32 accumulate)
    {
        const int smem_bytes = 12288 * sizeof(unsigned);  // 48KB
        cudaFuncSetAttribute(egemm_bf16,
                             cudaFuncAttributeMaxDynamicSharedMemorySize, smem_bytes);
        dim3 grid(HID / 64, (T_STEPS * BATCH) / 128);
        egemm_bf16<<<grid, 256, smem_bytes>>>(x, W_in, b_in, Eptr);
    }

    // 1.5) shift ncu's capture slot onto rnn_persistent
    ncu_shift_dummy<<<1, 32>>>();

    // 2) Persistent recurrence (R11: 512 threads, 16 warps, split-K 8)
    {
        const int smem_bytes = (32768 + 16384) * sizeof(unsigned);  // 192KB
        cudaFuncSetAttribute(rnn_persistent,
                             cudaFuncAttributeMaxDynamicSharedMemorySize, smem_bytes);
        rnn_persistent<<<GRID_P, 512, smem_bytes>>>(W_h, b_h);
    }

    // 3) Head + output tuple
    finalize_kernel<<<BATCH, 128>>>(hfin, st, W_o, b_o, out);
}